// round 1
// baseline (speedup 1.0000x reference)
#include <cuda_runtime.h>

// Problem constants
#define B_  8
#define T_  2048
#define S_  512
#define VD_ 512
#define AD_ 256
#define E_  512
#define H_  8
#define D_  64
#define BH_ (B_*H_)
#define CLAMP_ 50000.0f

// ---------------------------------------------------------------------------
// Device scratch (allocation-free rule: __device__ globals)
// ---------------------------------------------------------------------------
__device__ float g_q  [(size_t)B_*T_*E_];   // scaled queries  [B,T,E]
__device__ float g_k  [(size_t)B_*S_*E_];   // keys            [B,S,E]
__device__ float g_vv [(size_t)B_*T_*E_];   // val_v           [B,T,E]
__device__ float g_va [(size_t)B_*S_*E_];   // val_a           [B,S,E]
__device__ float g_va2[(size_t)B_*S_*E_];   // val_a * inv_sum (per b,h,s)
__device__ float g_sc [(size_t)BH_*T_*S_];  // scores -> unnormalized P'
__device__ float g_mx [BH_*S_];             // column max over t
__device__ float g_inv[BH_*S_];             // 1/sum over t of exp
__device__ float g_ov [(size_t)B_*T_*E_];   // attention out (visual), pre-proj
__device__ float g_oa [(size_t)B_*S_*E_];   // attention out (audio),  pre-proj

// ---------------------------------------------------------------------------
// Fast exp for x <= 0 (scores - max). ~7 FMA-class ops, rel err ~2e-6.
// Avoids the MUFU.EX2 throughput wall (67M exps -> ~25us of FMA instead).
// ---------------------------------------------------------------------------
__device__ __forceinline__ float fast_exp_neg(float x) {
    if (x < -87.0f) return 0.0f;
    float y = x * 1.442695040888963f;
    float n = rintf(y);
    float f = fmaf(n, -0.6931471805599453f, x);   // |f| <= ln2/2
    float p = 1.0f + f*(1.0f + f*(0.5f + f*(0.16666667f
                  + f*(0.041666668f + f*0.008333334f))));
    int in = (int)n;
    return p * __int_as_float((in + 127) << 23);
}

// ---------------------------------------------------------------------------
// Generic projection GEMM: C[M,N] = alpha * (A[M,K] @ W[K,N] + bias[N])
// 64x64 tile, BK=16, 256 threads, 4x4 per thread. Tile sizes divide all shapes.
// ---------------------------------------------------------------------------
__global__ void proj_gemm(const float* __restrict__ A, const float* __restrict__ W,
                          const float* __restrict__ bias, float* __restrict__ C,
                          int M, int K, int N, float alpha)
{
    __shared__ float As[16][64];
    __shared__ float Bs[16][64];
    const int bm = blockIdx.y * 64, bn = blockIdx.x * 64;
    const int tid = threadIdx.x;
    const int tx = tid & 15, ty = tid >> 4;
    float acc[4][4] = {};
    for (int k0 = 0; k0 < K; k0 += 16) {
        #pragma unroll
        for (int i = 0; i < 4; i++) {
            int idx = tid + i * 256;
            int r = idx >> 4, c = idx & 15;
            As[c][r] = A[(size_t)(bm + r) * K + (k0 + c)];
        }
        #pragma unroll
        for (int i = 0; i < 4; i++) {
            int idx = tid + i * 256;
            int c = idx >> 6, n = idx & 63;
            Bs[c][n] = W[(size_t)(k0 + c) * N + (bn + n)];
        }
        __syncthreads();
        #pragma unroll
        for (int kk = 0; kk < 16; kk++) {
            float4 av = reinterpret_cast<float4*>(As[kk])[ty];
            float4 bv = reinterpret_cast<float4*>(Bs[kk])[tx];
            float a[4] = {av.x, av.y, av.z, av.w};
            float b[4] = {bv.x, bv.y, bv.z, bv.w};
            #pragma unroll
            for (int i = 0; i < 4; i++)
                #pragma unroll
                for (int j = 0; j < 4; j++)
                    acc[i][j] = fmaf(a[i], b[j], acc[i][j]);
        }
        __syncthreads();
    }
    #pragma unroll
    for (int i = 0; i < 4; i++) {
        int row = bm + ty * 4 + i;
        #pragma unroll
        for (int j = 0; j < 4; j++) {
            int col = bn + tx * 4 + j;
            C[(size_t)row * N + col] = alpha * (acc[i][j] + bias[col]);
        }
    }
}

// ---------------------------------------------------------------------------
// scores[bh, t, s] = clamp( sum_d q[b,t,h,d] * k[b,s,h,d], +-50000 )
// grid (S/64, T/64, BH)
// ---------------------------------------------------------------------------
__global__ void scores_gemm()
{
    const int bh = blockIdx.z, b = bh / H_, h = bh % H_;
    const float* __restrict__ A  = g_q + (size_t)b * T_ * E_ + h * D_; // [T,D] lda=E
    const float* __restrict__ Bm = g_k + (size_t)b * S_ * E_ + h * D_; // [S,D] ldb=E
    float* __restrict__ C = g_sc + (size_t)bh * T_ * S_;
    __shared__ float As[16][64];
    __shared__ float Bs[16][64];
    const int bm = blockIdx.y * 64, bn = blockIdx.x * 64;
    const int tid = threadIdx.x;
    const int tx = tid & 15, ty = tid >> 4;
    float acc[4][4] = {};
    for (int k0 = 0; k0 < D_; k0 += 16) {
        #pragma unroll
        for (int i = 0; i < 4; i++) {
            int idx = tid + i * 256;
            int r = idx >> 4, c = idx & 15;
            As[c][r] = A[(size_t)(bm + r) * E_ + (k0 + c)];
        }
        #pragma unroll
        for (int i = 0; i < 4; i++) {
            int idx = tid + i * 256;
            int n = idx >> 4, c = idx & 15;
            Bs[c][n] = Bm[(size_t)(bn + n) * E_ + (k0 + c)];
        }
        __syncthreads();
        #pragma unroll
        for (int kk = 0; kk < 16; kk++) {
            float4 av = reinterpret_cast<float4*>(As[kk])[ty];
            float4 bv = reinterpret_cast<float4*>(Bs[kk])[tx];
            float a[4] = {av.x, av.y, av.z, av.w};
            float b2[4] = {bv.x, bv.y, bv.z, bv.w};
            #pragma unroll
            for (int i = 0; i < 4; i++)
                #pragma unroll
                for (int j = 0; j < 4; j++)
                    acc[i][j] = fmaf(a[i], b2[j], acc[i][j]);
        }
        __syncthreads();
    }
    #pragma unroll
    for (int i = 0; i < 4; i++) {
        int row = bm + ty * 4 + i;
        #pragma unroll
        for (int j = 0; j < 4; j++) {
            int col = bn + tx * 4 + j;
            float vsc = fminf(fmaxf(acc[i][j], -CLAMP_), CLAMP_);
            C[(size_t)row * S_ + col] = vsc;
        }
    }
}

// ---------------------------------------------------------------------------
// Per (bh, s): max over t.  grid (S/32, BH), 256 thr = 8 t-groups x 32 s-lanes
// ---------------------------------------------------------------------------
__global__ void col_max()
{
    const int bh = blockIdx.y;
    const int lane = threadIdx.x & 31, g = threadIdx.x >> 5;
    const int s = blockIdx.x * 32 + lane;
    const float* __restrict__ sc = g_sc + (size_t)bh * T_ * S_;
    float m = -3.4e38f;
    for (int t = g; t < T_; t += 8)
        m = fmaxf(m, sc[(size_t)t * S_ + s]);
    __shared__ float sm[8][32];
    sm[g][lane] = m;
    __syncthreads();
    if (g == 0) {
        float mm = sm[0][lane];
        #pragma unroll
        for (int i = 1; i < 8; i++) mm = fmaxf(mm, sm[i][lane]);
        g_mx[bh * S_ + s] = mm;
    }
}

// ---------------------------------------------------------------------------
// In-place: scores <- exp(scores - mx[s]); inv[s] = 1/sum_t
// ---------------------------------------------------------------------------
__global__ void exp_sum()
{
    const int bh = blockIdx.y;
    const int lane = threadIdx.x & 31, g = threadIdx.x >> 5;
    const int s = blockIdx.x * 32 + lane;
    float* __restrict__ sc = g_sc + (size_t)bh * T_ * S_;
    const float mx = g_mx[bh * S_ + s];
    float r = 0.0f;
    for (int t = g; t < T_; t += 8) {
        size_t idx = (size_t)t * S_ + s;
        float p = fast_exp_neg(sc[idx] - mx);
        sc[idx] = p;
        r += p;
    }
    __shared__ float sm[8][32];
    sm[g][lane] = r;
    __syncthreads();
    if (g == 0) {
        float ss = 0.0f;
        #pragma unroll
        for (int i = 0; i < 8; i++) ss += sm[i][lane];
        g_inv[bh * S_ + s] = 1.0f / ss;
    }
}

// val_a scaled by per-(b,h,s) inverse softmax sum -> g_va2
__global__ void scale_va()
{
    int i = blockIdx.x * 256 + threadIdx.x;       // B*S*E elements
    int de = i & (E_ - 1);
    int bs = i >> 9;                              // /E_ (512)
    int h = de >> 6;
    int b = bs / S_, s = bs & (S_ - 1);
    g_va2[i] = g_va[i] * g_inv[(b * H_ + h) * S_ + s];
}

// ---------------------------------------------------------------------------
// out_v[b,t,h,d] = sum_s P'[t,s] * va2[b,s,h,d]    (inv already folded into va2)
// grid (1, T/64, BH)
// ---------------------------------------------------------------------------
__global__ void out_v_gemm()
{
    const int bh = blockIdx.z, b = bh / H_, h = bh % H_;
    const float* __restrict__ A  = g_sc  + (size_t)bh * T_ * S_;        // [T,S]
    const float* __restrict__ Bm = g_va2 + (size_t)b * S_ * E_ + h * D_;// [S,64] ldb=E
    float* __restrict__ C = g_ov + (size_t)b * T_ * E_ + h * D_;
    __shared__ float As[16][64];
    __shared__ float Bs[16][64];
    const int bm = blockIdx.y * 64;
    const int tid = threadIdx.x;
    const int tx = tid & 15, ty = tid >> 4;
    float acc[4][4] = {};
    for (int k0 = 0; k0 < S_; k0 += 16) {
        #pragma unroll
        for (int i = 0; i < 4; i++) {
            int idx = tid + i * 256;
            int r = idx >> 4, c = idx & 15;
            As[c][r] = A[(size_t)(bm + r) * S_ + (k0 + c)];
        }
        #pragma unroll
        for (int i = 0; i < 4; i++) {
            int idx = tid + i * 256;
            int c = idx >> 6, n = idx & 63;
            Bs[c][n] = Bm[(size_t)(k0 + c) * E_ + n];
        }
        __syncthreads();
        #pragma unroll
        for (int kk = 0; kk < 16; kk++) {
            float4 av = reinterpret_cast<float4*>(As[kk])[ty];
            float4 bv = reinterpret_cast<float4*>(Bs[kk])[tx];
            float a[4] = {av.x, av.y, av.z, av.w};
            float b2[4] = {bv.x, bv.y, bv.z, bv.w};
            #pragma unroll
            for (int i = 0; i < 4; i++)
                #pragma unroll
                for (int j = 0; j < 4; j++)
                    acc[i][j] = fmaf(a[i], b2[j], acc[i][j]);
        }
        __syncthreads();
    }
    #pragma unroll
    for (int i = 0; i < 4; i++) {
        int row = bm + ty * 4 + i;
        #pragma unroll
        for (int j = 0; j < 4; j++) {
            int col = tx * 4 + j;
            C[(size_t)row * E_ + col] = acc[i][j];
        }
    }
}

// ---------------------------------------------------------------------------
// out_a[b,s,h,d] = inv[s] * sum_t P'[t,s] * vv[b,t,h,d]
// A is the transposed view of P' (A[s,t] = P'[t,s]).  grid (1, S/64, BH)
// ---------------------------------------------------------------------------
__global__ void out_a_gemm()
{
    const int bh = blockIdx.z, b = bh / H_, h = bh % H_;
    const float* __restrict__ A  = g_sc + (size_t)bh * T_ * S_;         // [T,S]
    const float* __restrict__ Bm = g_vv + (size_t)b * T_ * E_ + h * D_; // [T,64] ldb=E
    float* __restrict__ C = g_oa + (size_t)b * S_ * E_ + h * D_;
    __shared__ float As[16][64];
    __shared__ float Bs[16][64];
    const int bm = blockIdx.y * 64;   // s base
    const int tid = threadIdx.x;
    const int tx = tid & 15, ty = tid >> 4;
    float acc[4][4] = {};
    for (int k0 = 0; k0 < T_; k0 += 16) {
        #pragma unroll
        for (int i = 0; i < 4; i++) {
            int idx = tid + i * 256;
            int r = idx & 63, c = idx >> 6;
            As[c][r] = A[(size_t)(k0 + c) * S_ + (bm + r)];
        }
        #pragma unroll
        for (int i = 0; i < 4; i++) {
            int idx = tid + i * 256;
            int c = idx >> 6, n = idx & 63;
            Bs[c][n] = Bm[(size_t)(k0 + c) * E_ + n];
        }
        __syncthreads();
        #pragma unroll
        for (int kk = 0; kk < 16; kk++) {
            float4 av = reinterpret_cast<float4*>(As[kk])[ty];
            float4 bv = reinterpret_cast<float4*>(Bs[kk])[tx];
            float a[4] = {av.x, av.y, av.z, av.w};
            float b2[4] = {bv.x, bv.y, bv.z, bv.w};
            #pragma unroll
            for (int i = 0; i < 4; i++)
                #pragma unroll
                for (int j = 0; j < 4; j++)
                    acc[i][j] = fmaf(a[i], b2[j], acc[i][j]);
        }
        __syncthreads();
    }
    #pragma unroll
    for (int i = 0; i < 4; i++) {
        int srow = bm + ty * 4 + i;
        float inv = g_inv[bh * S_ + srow];
        #pragma unroll
        for (int j = 0; j < 4; j++) {
            int col = tx * 4 + j;
            C[(size_t)srow * E_ + col] = acc[i][j] * inv;
        }
    }
}

// ---------------------------------------------------------------------------
// Launch
// ---------------------------------------------------------------------------
extern "C" void kernel_launch(void* const* d_in, const int* in_sizes, int n_in,
                              void* d_out, int out_size)
{
    const float* v    = (const float*)d_in[0];
    const float* a    = (const float*)d_in[1];
    const float* w_vq = (const float*)d_in[2];
    const float* b_vq = (const float*)d_in[3];
    const float* w_ak = (const float*)d_in[4];
    const float* b_ak = (const float*)d_in[5];
    const float* w_vv = (const float*)d_in[6];
    const float* b_vv = (const float*)d_in[7];
    const float* w_av = (const float*)d_in[8];
    const float* b_av = (const float*)d_in[9];
    const float* w_ov = (const float*)d_in[10];
    const float* b_ov = (const float*)d_in[11];
    const float* w_oa = (const float*)d_in[12];
    const float* b_oa = (const float*)d_in[13];
    float* out = (float*)d_out;

    float *pq, *pk, *pvv, *pva, *pov, *poa;
    cudaGetSymbolAddress((void**)&pq,  g_q);
    cudaGetSymbolAddress((void**)&pk,  g_k);
    cudaGetSymbolAddress((void**)&pvv, g_vv);
    cudaGetSymbolAddress((void**)&pva, g_va);
    cudaGetSymbolAddress((void**)&pov, g_ov);
    cudaGetSymbolAddress((void**)&poa, g_oa);

    const float scale = 0.125f;  // D^-0.5

    // input projections
    proj_gemm<<<dim3(E_/64, (B_*T_)/64), 256>>>(v, w_vq, b_vq, pq,  B_*T_, VD_, E_, scale);
    proj_gemm<<<dim3(E_/64, (B_*S_)/64), 256>>>(a, w_ak, b_ak, pk,  B_*S_, AD_, E_, 1.0f);
    proj_gemm<<<dim3(E_/64, (B_*T_)/64), 256>>>(v, w_vv, b_vv, pvv, B_*T_, VD_, E_, 1.0f);
    proj_gemm<<<dim3(E_/64, (B_*S_)/64), 256>>>(a, w_av, b_av, pva, B_*S_, AD_, E_, 1.0f);

    // scores + shared softmax stats (softmax over T serves BOTH attn paths)
    scores_gemm<<<dim3(S_/64, T_/64, BH_), 256>>>();
    col_max <<<dim3(S_/32, BH_), 256>>>();
    exp_sum <<<dim3(S_/32, BH_), 256>>>();
    scale_va<<<(B_*S_*E_)/256, 256>>>();

    // attention-weighted values
    out_v_gemm<<<dim3(1, T_/64, BH_), 256>>>();
    out_a_gemm<<<dim3(1, S_/64, BH_), 256>>>();

    // output projections straight into d_out (out_v first, then out_a)
    proj_gemm<<<dim3(VD_/64, (B_*T_)/64), 256>>>(pov, w_ov, b_ov, out, B_*T_, E_, VD_, 1.0f);
    proj_gemm<<<dim3(AD_/64, (B_*S_)/64), 256>>>(poa, w_oa, b_oa,
                                                 out + (size_t)B_*T_*VD_, B_*S_, E_, AD_, 1.0f);
}

// round 3
// speedup vs baseline: 1.5863x; 1.5863x over previous
#include <cuda_runtime.h>
#include <cuda_bf16.h>
#include <mma.h>
#include <cstdint>

using namespace nvcuda;

#define B_  8
#define T_  2048
#define S_  512
#define VD_ 512
#define AD_ 256
#define E_  512
#define H_  8
#define D_  64
#define BH_ (B_*H_)
#define CLAMP_ 50000.0f

// ---------------------------------------------------------------------------
// Device scratch
// ---------------------------------------------------------------------------
__device__ float g_q  [(size_t)B_*T_*E_];
__device__ float g_k  [(size_t)B_*S_*E_];
__device__ float g_vv [(size_t)B_*T_*E_];
__device__ float g_va [(size_t)B_*S_*E_];
__device__ float g_va2[(size_t)B_*S_*E_];
__device__ float g_sc [(size_t)BH_*T_*S_];
__device__ float g_mx [BH_*S_];
__device__ float g_inv[BH_*S_];
__device__ float g_ov [(size_t)B_*T_*E_];
__device__ float g_oa [(size_t)B_*S_*E_];

// ---------------------------------------------------------------------------
// GEMM argument pack
// AMODE: 0 = A[M,K], row stride lda      | 1 = A stored [K,M], row stride lda
// BMODE: 0 = B stored [N,K] (contig K)   | 1 = B stored [K,N] (contig N)
// EPI:   0 none | 1 alpha*(acc+bias[n])  | 2 clamp | 3 * rowscale[m]
// ---------------------------------------------------------------------------
struct GArgs {
    const float* A; int lda; long sAb, sAh;
    const float* B; int ldb; long sBb, sBh;
    float*       C; int ldc; long sCb, sCh;
    int K;
    const float* bias;
    float alpha;
    const float* rs; int rs_stride;
};

#define LDA_S 40                      // bf16 elements per A smem row (32 + 8 pad)
#define KC    32                      // K chunk (fp32 elems)

__device__ __forceinline__ void split2(float x, __nv_bfloat16& h, __nv_bfloat16& l) {
    h = __float2bfloat16(x);
    l = __float2bfloat16(x - __bfloat162float(h));
}

// ---------------------------------------------------------------------------
// global -> registers
// ---------------------------------------------------------------------------
template<int NT, int AMODE, int BMODE>
__device__ __forceinline__ void ldg_tiles(const GArgs& g, const float* Ap,
                                          const float* Bp, int m0, int n0, int k0,
                                          float4 (&ra)[4], float4 (&rb)[NT/32], int tid)
{
    #pragma unroll
    for (int i = 0; i < 4; i++) {
        int qid = tid + i * 256;
        if (AMODE == 0) {
            int r = qid >> 3, c4 = (qid & 7) * 4;
            ra[i] = *reinterpret_cast<const float4*>(Ap + (size_t)(m0 + r) * g.lda + k0 + c4);
        } else {
            int k = qid >> 5, m4 = (qid & 31) * 4;
            ra[i] = *reinterpret_cast<const float4*>(Ap + (size_t)(k0 + k) * g.lda + m0 + m4);
        }
    }
    #pragma unroll
    for (int i = 0; i < NT / 32; i++) {
        int qid = tid + i * 256;
        if (BMODE == 0) {
            int n = qid >> 3, k4 = (qid & 7) * 4;
            rb[i] = *reinterpret_cast<const float4*>(Bp + (size_t)(n0 + n) * g.ldb + k0 + k4);
        } else {
            int k = qid / (NT / 4), n4 = (qid % (NT / 4)) * 4;
            rb[i] = *reinterpret_cast<const float4*>(Bp + (size_t)(k0 + k) * g.ldb + n0 + n4);
        }
    }
}

// ---------------------------------------------------------------------------
// registers -> smem (bf16 hi/lo split)
// ---------------------------------------------------------------------------
template<int NT, int AMODE, int BMODE>
__device__ __forceinline__ void sts_tiles(__nv_bfloat16* Ah, __nv_bfloat16* Al,
                                          __nv_bfloat16* Bh, __nv_bfloat16* Bl,
                                          const float4 (&ra)[4], const float4 (&rb)[NT/32],
                                          int tid)
{
    const int LDB_S = NT + 8;
    #pragma unroll
    for (int i = 0; i < 4; i++) {
        int qid = tid + i * 256;
        float v[4] = {ra[i].x, ra[i].y, ra[i].z, ra[i].w};
        __nv_bfloat16 h[4], l[4];
        #pragma unroll
        for (int j = 0; j < 4; j++) split2(v[j], h[j], l[j]);
        if (AMODE == 0) {
            int r = qid >> 3, c4 = (qid & 7) * 4;
            __nv_bfloat16* ph = Ah + r * LDA_S + c4;
            __nv_bfloat16* pl = Al + r * LDA_S + c4;
            *reinterpret_cast<__nv_bfloat162*>(ph)     = __halves2bfloat162(h[0], h[1]);
            *reinterpret_cast<__nv_bfloat162*>(ph + 2) = __halves2bfloat162(h[2], h[3]);
            *reinterpret_cast<__nv_bfloat162*>(pl)     = __halves2bfloat162(l[0], l[1]);
            *reinterpret_cast<__nv_bfloat162*>(pl + 2) = __halves2bfloat162(l[2], l[3]);
        } else {
            int k = qid >> 5, m4 = (qid & 31) * 4;
            #pragma unroll
            for (int j = 0; j < 4; j++) {
                Ah[(m4 + j) * LDA_S + k] = h[j];
                Al[(m4 + j) * LDA_S + k] = l[j];
            }
        }
    }
    #pragma unroll
    for (int i = 0; i < NT / 32; i++) {
        int qid = tid + i * 256;
        float v[4] = {rb[i].x, rb[i].y, rb[i].z, rb[i].w};
        __nv_bfloat16 h[4], l[4];
        #pragma unroll
        for (int j = 0; j < 4; j++) split2(v[j], h[j], l[j]);
        if (BMODE == 0) {
            int n = qid >> 3, k4 = (qid & 7) * 4;
            #pragma unroll
            for (int j = 0; j < 4; j++) {
                Bh[(k4 + j) * LDB_S + n] = h[j];
                Bl[(k4 + j) * LDB_S + n] = l[j];
            }
        } else {
            int k = qid / (NT / 4), n4 = (qid % (NT / 4)) * 4;
            __nv_bfloat16* ph = Bh + k * LDB_S + n4;
            __nv_bfloat16* pl = Bl + k * LDB_S + n4;
            *reinterpret_cast<__nv_bfloat162*>(ph)     = __halves2bfloat162(h[0], h[1]);
            *reinterpret_cast<__nv_bfloat162*>(ph + 2) = __halves2bfloat162(h[2], h[3]);
            *reinterpret_cast<__nv_bfloat162*>(pl)     = __halves2bfloat162(l[0], l[1]);
            *reinterpret_cast<__nv_bfloat162*>(pl + 2) = __halves2bfloat162(l[2], l[3]);
        }
    }
}

// ---------------------------------------------------------------------------
// wmma bf16 GEMM with 2-term split (ah*bh + al*bh + ah*bl), fp32 accumulate.
// C tile 128 x NT. 8 warps as 4(M) x 2(N); warp tile 32 x NT/2.
// ---------------------------------------------------------------------------
template<int NT, int AMODE, int BMODE, int EPI>
__global__ void __launch_bounds__(256, 1) mma_gemm(GArgs g)
{
    extern __shared__ char smem[];
    const int tid = threadIdx.x, wid = tid >> 5;
    const int wm = wid & 3, wn = wid >> 2;
    const int z = blockIdx.z, zb = z >> 3, zh = z & 7;
    const int m0 = blockIdx.y * 128, n0 = blockIdx.x * NT;

    const float* Ap = g.A + (long)zb * g.sAb + (long)zh * g.sAh;
    const float* Bp = g.B + (long)zb * g.sBb + (long)zh * g.sBh;
    float*       Cp = g.C + (long)zb * g.sCb + (long)zh * g.sCh;

    constexpr int LDB_S = NT + 8;
    constexpr int ASZ = 128 * LDA_S * 2;        // bytes per A half-buffer
    constexpr int BSZ = KC * LDB_S * 2;         // bytes per B half-buffer
    constexpr int NF  = NT / 32;                // n-frags per warp

    auto Abuf = [&](int b, int h) {
        return reinterpret_cast<__nv_bfloat16*>(smem + b * 2 * ASZ + h * ASZ);
    };
    auto Bbuf = [&](int b, int h) {
        return reinterpret_cast<__nv_bfloat16*>(smem + 4 * ASZ + b * 2 * BSZ + h * BSZ);
    };

    wmma::fragment<wmma::accumulator, 16, 16, 16, float> acc[2][NF];
    #pragma unroll
    for (int m = 0; m < 2; m++)
        #pragma unroll
        for (int n = 0; n < NF; n++)
            wmma::fill_fragment(acc[m][n], 0.0f);

    const int nc = g.K / KC;
    float4 ra[4];
    float4 rb[NF];

    ldg_tiles<NT, AMODE, BMODE>(g, Ap, Bp, m0, n0, 0, ra, rb, tid);
    sts_tiles<NT, AMODE, BMODE>(Abuf(0,0), Abuf(0,1), Bbuf(0,0), Bbuf(0,1), ra, rb, tid);
    __syncthreads();

    for (int c = 0; c < nc; c++) {
        int cur = c & 1;
        if (c + 1 < nc)
            ldg_tiles<NT, AMODE, BMODE>(g, Ap, Bp, m0, n0, (c + 1) * KC, ra, rb, tid);

        const __nv_bfloat16* Ah = Abuf(cur, 0);
        const __nv_bfloat16* Al = Abuf(cur, 1);
        const __nv_bfloat16* Bh = Bbuf(cur, 0);
        const __nv_bfloat16* Bl = Bbuf(cur, 1);

        #pragma unroll
        for (int ks = 0; ks < KC / 16; ks++) {
            wmma::fragment<wmma::matrix_a, 16, 16, 16, __nv_bfloat16, wmma::row_major> ah[2], al[2];
            #pragma unroll
            for (int m = 0; m < 2; m++) {
                const __nv_bfloat16* pa = Ah + (wm * 32 + m * 16) * LDA_S + ks * 16;
                const __nv_bfloat16* qa = Al + (wm * 32 + m * 16) * LDA_S + ks * 16;
                wmma::load_matrix_sync(ah[m], pa, LDA_S);
                wmma::load_matrix_sync(al[m], qa, LDA_S);
            }
            #pragma unroll
            for (int n = 0; n < NF; n++) {
                wmma::fragment<wmma::matrix_b, 16, 16, 16, __nv_bfloat16, wmma::row_major> bh, bl;
                const __nv_bfloat16* pb = Bh + (ks * 16) * LDB_S + wn * (NT / 2) + n * 16;
                const __nv_bfloat16* qb = Bl + (ks * 16) * LDB_S + wn * (NT / 2) + n * 16;
                wmma::load_matrix_sync(bh, pb, LDB_S);
                wmma::load_matrix_sync(bl, qb, LDB_S);
                #pragma unroll
                for (int m = 0; m < 2; m++) {
                    wmma::mma_sync(acc[m][n], ah[m], bh, acc[m][n]);
                    wmma::mma_sync(acc[m][n], al[m], bh, acc[m][n]);
                    wmma::mma_sync(acc[m][n], ah[m], bl, acc[m][n]);
                }
            }
        }
        if (c + 1 < nc) {
            int nxt = cur ^ 1;
            sts_tiles<NT, AMODE, BMODE>(Abuf(nxt,0), Abuf(nxt,1), Bbuf(nxt,0), Bbuf(nxt,1),
                                        ra, rb, tid);
        }
        __syncthreads();
    }

    // ---- epilogue: frags -> smem (reuse buffers) -> global with EPI ----
    float* Cs = reinterpret_cast<float*>(smem);
    constexpr int LDS_C = NT + 4;
    #pragma unroll
    for (int m = 0; m < 2; m++)
        #pragma unroll
        for (int n = 0; n < NF; n++)
            wmma::store_matrix_sync(Cs + (wm * 32 + m * 16) * LDS_C + wn * (NT / 2) + n * 16,
                                    acc[m][n], LDS_C, wmma::mem_row_major);
    __syncthreads();

    constexpr int F4R = NT / 4;              // float4s per row
    constexpr int ITERS = 128 * F4R / 256;
    #pragma unroll
    for (int it = 0; it < ITERS; it++) {
        int qid = tid + it * 256;
        int r = qid / F4R, c4 = (qid % F4R) * 4;
        float4 v = *reinterpret_cast<float4*>(Cs + r * LDS_C + c4);
        float* pv = &v.x;
        if (EPI == 1) {
            #pragma unroll
            for (int j = 0; j < 4; j++)
                pv[j] = g.alpha * (pv[j] + __ldg(g.bias + n0 + c4 + j));
        } else if (EPI == 2) {
            #pragma unroll
            for (int j = 0; j < 4; j++)
                pv[j] = fminf(fmaxf(pv[j], -CLAMP_), CLAMP_);
        } else if (EPI == 3) {
            float rsv = __ldg(g.rs + (size_t)z * g.rs_stride + m0 + r);
            #pragma unroll
            for (int j = 0; j < 4; j++) pv[j] *= rsv;
        }
        *reinterpret_cast<float4*>(Cp + (size_t)(m0 + r) * g.ldc + n0 + c4) = v;
    }
}

// ---------------------------------------------------------------------------
// softmax stat passes (shared softmax over T serves BOTH attention paths)
// ---------------------------------------------------------------------------
__device__ __forceinline__ float fast_exp_neg(float x) {
    if (x < -87.0f) return 0.0f;
    float y = x * 1.442695040888963f;
    float n = rintf(y);
    float f = fmaf(n, -0.6931471805599453f, x);
    float p = 1.0f + f*(1.0f + f*(0.5f + f*(0.16666667f
                  + f*(0.041666668f + f*0.008333334f))));
    return p * __int_as_float(((int)n + 127) << 23);
}

__global__ void col_max()
{
    const int bh = blockIdx.y;
    const int lane = threadIdx.x & 31, gg = threadIdx.x >> 5;
    const int s = blockIdx.x * 32 + lane;
    const float* __restrict__ sc = g_sc + (size_t)bh * T_ * S_;
    float m = -3.4e38f;
    for (int t = gg; t < T_; t += 8)
        m = fmaxf(m, sc[(size_t)t * S_ + s]);
    __shared__ float sm[8][32];
    sm[gg][lane] = m;
    __syncthreads();
    if (gg == 0) {
        float mm = sm[0][lane];
        #pragma unroll
        for (int i = 1; i < 8; i++) mm = fmaxf(mm, sm[i][lane]);
        g_mx[bh * S_ + s] = mm;
    }
}

__global__ void exp_sum()
{
    const int bh = blockIdx.y;
    const int lane = threadIdx.x & 31, gg = threadIdx.x >> 5;
    const int s = blockIdx.x * 32 + lane;
    float* __restrict__ sc = g_sc + (size_t)bh * T_ * S_;
    const float mx = g_mx[bh * S_ + s];
    float r = 0.0f;
    for (int t = gg; t < T_; t += 8) {
        size_t idx = (size_t)t * S_ + s;
        float p = fast_exp_neg(sc[idx] - mx);
        sc[idx] = p;
        r += p;
    }
    __shared__ float sm[8][32];
    sm[gg][lane] = r;
    __syncthreads();
    if (gg == 0) {
        float ss = 0.0f;
        #pragma unroll
        for (int i = 0; i < 8; i++) ss += sm[i][lane];
        g_inv[bh * S_ + s] = 1.0f / ss;
    }
}

__global__ void scale_va()
{
    int i = blockIdx.x * 256 + threadIdx.x;
    int de = i & (E_ - 1);
    int bs = i >> 9;
    int h = de >> 6;
    int b = bs / S_, s = bs & (S_ - 1);
    g_va2[i] = g_va[i] * g_inv[(b * H_ + h) * S_ + s];
}

// ---------------------------------------------------------------------------
// Launch
// ---------------------------------------------------------------------------
extern "C" void kernel_launch(void* const* d_in, const int* in_sizes, int n_in,
                              void* d_out, int out_size)
{
    const float* v    = (const float*)d_in[0];
    const float* a    = (const float*)d_in[1];
    const float* w_vq = (const float*)d_in[2];
    const float* b_vq = (const float*)d_in[3];
    const float* w_ak = (const float*)d_in[4];
    const float* b_ak = (const float*)d_in[5];
    const float* w_vv = (const float*)d_in[6];
    const float* b_vv = (const float*)d_in[7];
    const float* w_av = (const float*)d_in[8];
    const float* b_av = (const float*)d_in[9];
    const float* w_ov = (const float*)d_in[10];
    const float* b_ov = (const float*)d_in[11];
    const float* w_oa = (const float*)d_in[12];
    const float* b_oa = (const float*)d_in[13];
    float* out = (float*)d_out;

    float *pq, *pk, *pvv, *pva, *pva2, *psc, *pinv, *pov, *poa;
    cudaGetSymbolAddress((void**)&pq,   g_q);
    cudaGetSymbolAddress((void**)&pk,   g_k);
    cudaGetSymbolAddress((void**)&pvv,  g_vv);
    cudaGetSymbolAddress((void**)&pva,  g_va);
    cudaGetSymbolAddress((void**)&pva2, g_va2);
    cudaGetSymbolAddress((void**)&psc,  g_sc);
    cudaGetSymbolAddress((void**)&pinv, g_inv);
    cudaGetSymbolAddress((void**)&pov,  g_ov);
    cudaGetSymbolAddress((void**)&poa,  g_oa);

    // smem sizes: pipe = 4*ASZ + 4*BSZ; epi = 128*(NT+4)*4 (pipe dominates)
    const int ASZ = 128 * LDA_S * 2;
    const int SM128 = 4 * ASZ + 4 * (KC * (128 + 8) * 2);   // 75776
    const int SM64  = 4 * ASZ + 4 * (KC * (64 + 8) * 2);    // 59392
    cudaFuncSetAttribute(mma_gemm<128,0,1,1>, cudaFuncAttributeMaxDynamicSharedMemorySize, SM128);
    cudaFuncSetAttribute(mma_gemm<128,0,0,2>, cudaFuncAttributeMaxDynamicSharedMemorySize, SM128);
    cudaFuncSetAttribute(mma_gemm<64,0,1,0>,  cudaFuncAttributeMaxDynamicSharedMemorySize, SM64);
    cudaFuncSetAttribute(mma_gemm<64,1,1,3>,  cudaFuncAttributeMaxDynamicSharedMemorySize, SM64);

    GArgs g{};

    // ---- input projections (EPI=1: alpha*(acc+bias)) ----
    g = GArgs{ v, VD_, 0, 0,  w_vq, E_, 0, 0,  pq, E_, 0, 0,  VD_, b_vq, 0.125f, nullptr, 0 };
    mma_gemm<128,0,1,1><<<dim3(E_/128, (B_*T_)/128, 1), 256, SM128>>>(g);
    g = GArgs{ a, AD_, 0, 0,  w_ak, E_, 0, 0,  pk, E_, 0, 0,  AD_, b_ak, 1.0f, nullptr, 0 };
    mma_gemm<128,0,1,1><<<dim3(E_/128, (B_*S_)/128, 1), 256, SM128>>>(g);
    g = GArgs{ v, VD_, 0, 0,  w_vv, E_, 0, 0,  pvv, E_, 0, 0,  VD_, b_vv, 1.0f, nullptr, 0 };
    mma_gemm<128,0,1,1><<<dim3(E_/128, (B_*T_)/128, 1), 256, SM128>>>(g);
    g = GArgs{ a, AD_, 0, 0,  w_av, E_, 0, 0,  pva, E_, 0, 0,  AD_, b_av, 1.0f, nullptr, 0 };
    mma_gemm<128,0,1,1><<<dim3(E_/128, (B_*S_)/128, 1), 256, SM128>>>(g);

    // ---- scores = clamp(q @ k^T) per (b,h)  (EPI=2) ----
    g = GArgs{ pq, E_, (long)T_*E_, D_,
               pk, E_, (long)S_*E_, D_,
               psc, S_, (long)H_*T_*S_, (long)T_*S_,
               D_, nullptr, 1.0f, nullptr, 0 };
    mma_gemm<128,0,0,2><<<dim3(S_/128, T_/128, BH_), 256, SM128>>>(g);

    // ---- shared softmax stats over T ----
    col_max <<<dim3(S_/32, BH_), 256>>>();
    exp_sum <<<dim3(S_/32, BH_), 256>>>();
    scale_va<<<(B_*S_*E_)/256, 256>>>();

    // ---- out_v = P' @ va2 (inv folded into va2) ----
    g = GArgs{ psc, S_, (long)H_*T_*S_, (long)T_*S_,
               pva2, E_, (long)S_*E_, D_,
               pov, E_, (long)T_*E_, D_,
               S_, nullptr, 1.0f, nullptr, 0 };
    mma_gemm<64,0,1,0><<<dim3(1, T_/128, BH_), 256, SM64>>>(g);

    // ---- out_a = inv[s] * (P'^T @ vv) ----
    g = GArgs{ psc, S_, (long)H_*T_*S_, (long)T_*S_,
               pvv, E_, (long)T_*E_, D_,
               poa, E_, (long)S_*E_, D_,
               T_, nullptr, 1.0f, pinv, S_ };
    mma_gemm<64,1,1,3><<<dim3(1, S_/128, BH_), 256, SM64>>>(g);

    // ---- output projections into d_out ----
    g = GArgs{ pov, E_, 0, 0,  w_ov, VD_, 0, 0,  out, VD_, 0, 0,  E_, b_ov, 1.0f, nullptr, 0 };
    mma_gemm<128,0,1,1><<<dim3(VD_/128, (B_*T_)/128, 1), 256, SM128>>>(g);
    g = GArgs{ poa, E_, 0, 0,  w_oa, AD_, 0, 0,
               out + (size_t)B_*T_*VD_, AD_, 0, 0,  E_, b_oa, 1.0f, nullptr, 0 };
    mma_gemm<128,0,1,1><<<dim3(AD_/128, (B_*S_)/128, 1), 256, SM128>>>(g);
}